// round 12
// baseline (speedup 1.0000x reference)
#include <cuda_runtime.h>
#include <cuda_bf16.h>
#include <cstdint>

#define N_NODES 50000
#define N_EDGES 800000
#define IN_CH 64
#define HID 128
#define NTHREADS 256

// Scratch (device globals -- no allocation allowed)
__device__ int   g_deg[N_NODES];
__device__ int   g_off[N_NODES];
__device__ int   g_cur[N_NODES];
__device__ int   g_part[64];
__device__ int   g_ctr;
__device__ int2  g_edge[N_EDGES];           // {src, bits(weight)}
__device__ float g_h2[N_NODES * HID];
__device__ uint32_t g_wh[40960], g_wl[40960];   // pre-split weight planes

// weight plane offsets (bf16x2 words)
#define WOFF_REL0  0
#define WOFF_ROOT0 4096
#define WOFF_RO0   8192
#define WOFF_REL1  16384
#define WOFF_ROOT1 24576
#define WOFF_RO1   32768

// ---------------------------------------------------------------------------
// bf16 helpers
// ---------------------------------------------------------------------------
__device__ __forceinline__ uint32_t pack_bf2(float a, float b) {
    __nv_bfloat162 t = __floats2bfloat162_rn(a, b);
    return *reinterpret_cast<uint32_t*>(&t);
}
__device__ __forceinline__ void split_bf2(float a, float b, uint32_t& hi, uint32_t& lo) {
    float ah = __bfloat162float(__float2bfloat16_rn(a));
    float bh = __bfloat162float(__float2bfloat16_rn(b));
    hi = pack_bf2(ah, bh);
    lo = pack_bf2(a - ah, b - bh);
}
__device__ __forceinline__ void mma_bf16(float c[4], const uint32_t a[4], const uint32_t b[2]) {
    asm volatile(
        "mma.sync.aligned.m16n8k16.row.col.f32.bf16.bf16.f32 "
        "{%0,%1,%2,%3}, {%4,%5,%6,%7}, {%8,%9}, {%0,%1,%2,%3};"
        : "+f"(c[0]), "+f"(c[1]), "+f"(c[2]), "+f"(c[3])
        : "r"(a[0]), "r"(a[1]), "r"(a[2]), "r"(a[3]), "r"(b[0]), "r"(b[1]));
}

// ---------------------------------------------------------------------------
// Prep: split weights into hi/lo planes; zero deg; zero ctr
// ---------------------------------------------------------------------------
__global__ void prep(const float* __restrict__ Wrel0, const float* __restrict__ Wroot0,
                     const float* __restrict__ Wro0,  const float* __restrict__ Wrel1,
                     const float* __restrict__ Wroot1,const float* __restrict__ Wro1, int n) {
    int i = blockIdx.x * blockDim.x + threadIdx.x;
    if (i < n) g_deg[i] = 0;
    if (i == 0) g_ctr = 0;
    if (i >= 40960) return;
    const float* src; int off;
    if      (i < 4096)  { src = Wrel0;  off = i; }
    else if (i < 8192)  { src = Wroot0; off = i - 4096; }
    else if (i < 16384) { src = Wro0;   off = i - 8192; }
    else if (i < 24576) { src = Wrel1;  off = i - 16384; }
    else if (i < 32768) { src = Wroot1; off = i - 24576; }
    else                { src = Wro1;   off = i - 32768; }
    float2 v = reinterpret_cast<const float2*>(src)[off];
    uint32_t h, l; split_bf2(v.x, v.y, h, l);
    g_wh[i] = h; g_wl[i] = l;
}

// ---------------------------------------------------------------------------
// CSR build: histogram -> shuffle scan (fused partial fixup) -> apply -> fill
// ---------------------------------------------------------------------------
__global__ void hist(const int* __restrict__ ei, int E) {
    int e = blockIdx.x * blockDim.x + threadIdx.x;
    if (e < E) atomicAdd(&g_deg[ei[E + e]], 1);
}
__global__ void scan1(int n) {
    __shared__ int wsum[32];
    __shared__ int s_total;
    __shared__ bool isLast;
    int tid  = threadIdx.x;
    int lane = tid & 31, wid = tid >> 5;
    int i = blockIdx.x * 1024 + tid;
    int v = (i < n) ? g_deg[i] : 0;
    int inc = v;
#pragma unroll
    for (int o = 1; o < 32; o <<= 1) {
        int t = __shfl_up_sync(0xFFFFFFFFu, inc, o);
        if (lane >= o) inc += t;
    }
    if (lane == 31) wsum[wid] = inc;
    __syncthreads();
    if (wid == 0) {
        int wv = wsum[lane];
        int winc = wv;
#pragma unroll
        for (int o = 1; o < 32; o <<= 1) {
            int t = __shfl_up_sync(0xFFFFFFFFu, winc, o);
            if (lane >= o) winc += t;
        }
        wsum[lane] = winc - wv;          // exclusive warp offset
        if (lane == 31) s_total = winc;  // block total
    }
    __syncthreads();
    if (i < n) g_off[i] = inc - v + wsum[wid];
    if (tid == 0) g_part[blockIdx.x] = s_total;
    __threadfence();
    if (tid == 0) isLast = (atomicAdd(&g_ctr, 1) == (int)gridDim.x - 1);
    __syncthreads();
    if (isLast) {
        __shared__ int p[64];
        int nb = gridDim.x;
        if (tid < 64) p[tid] = (tid < nb) ? g_part[tid] : 0;
        __syncthreads();
        if (tid == 0) {
            int run = 0;
            for (int b = 0; b < nb; b++) { int t = p[b]; p[b] = run; run += t; }
        }
        __syncthreads();
        if (tid < nb) g_part[tid] = p[tid];
    }
}
__global__ void scan3(int n) {
    int i = blockIdx.x * blockDim.x + threadIdx.x;
    if (i < n) {
        int o = g_off[i] + g_part[i >> 10];
        g_off[i] = o;
        g_cur[i] = o;
    }
}
__global__ void fill(const int* __restrict__ ei, const float* __restrict__ ew, int E) {
    int e = blockIdx.x * blockDim.x + threadIdx.x;
    if (e >= E) return;
    int dst = ei[E + e];
    int p = atomicAdd(&g_cur[dst], 1);
    g_edge[p] = make_int2(ei[e], __float_as_int(ew[e]));
}

// ---------------------------------------------------------------------------
// Fully fused layer (gather + conv + readout [+head]), 3xBF16 mma:
//   agg[r] = (sum_e w_e * H[src_e]) / max(deg,1)       (gathered in-kernel)
//   t  = relu( agg@Wrel^T + H@Wroot^T + bias1 )
//   y  = relu( t@Wro^T + bias2 )    /  HEAD: out = y @ Wprd^T + bprd
// CTA 128x128, 8 warps (4x2), warp tile 32x64 (2x8 m16n8k16).
// Gf (full-width, FW stride) holds: gather agg -> root A chunks (SW) -> t.
// ---------------------------------------------------------------------------
#define SW 36
#define FW 68

template <int KTC, bool HEAD>
__global__ void __launch_bounds__(NTHREADS, 2)
fused_layer(const float* __restrict__ H, int woff_rel, int woff_root,
            const float* __restrict__ bias1,
            int woff3, const float* __restrict__ bias2,
            const float* __restrict__ Wprd, const float* __restrict__ bprd,
            float* __restrict__ Y, int M)
{
    extern __shared__ uint32_t sm[];
    uint32_t* BsH = sm;                    // [128][SW]
    uint32_t* BsL = sm + 128 * SW;
    uint32_t* GfH = sm + 2 * 128 * SW;     // [128][FW] multi-purpose A region
    uint32_t* GfL = sm + 2 * 128 * SW + 128 * FW;
    __shared__ float red[128][2];

    int tid  = threadIdx.x;
    int lane = tid & 31;
    int warp = tid >> 5;
    int wm   = (warp >> 1) * 32;
    int wn   = (warp & 1) * 64;
    int gr   = lane >> 2;
    int gc   = lane & 3;
    int m0   = blockIdx.x * 128;

    constexpr int NCH = KTC / 64;
    constexpr int KTW = KTC / 2;

    float c[2][8][4];
#pragma unroll
    for (int mt = 0; mt < 2; mt++)
#pragma unroll
        for (int nt = 0; nt < 8; nt++)
#pragma unroll
            for (int j = 0; j < 4; j++) c[mt][nt][j] = 0.0f;

    // ---------------- gather: agg rows -> Gf (FW stride) ----------------
    for (int i = 0; i < 16; i++) {
        int r = warp * 16 + i;
        int grow = m0 + r;
        int start = 0, d = 0;
        if (grow < M) { start = g_off[grow]; d = g_deg[grow]; }

        if (KTC == 128) {
            float4 acc = make_float4(0.f, 0.f, 0.f, 0.f);
            for (int base = 0; base < d; base += 32) {
                int mm = min(32, d - base);
                int s = 0; float w = 0.f;
                if (lane < mm) {
                    int2 e = g_edge[start + base + lane];
                    s = e.x; w = __int_as_float(e.y);
                }
                int j = 0;
                for (; j + 4 <= mm; j += 4) {
                    int s0 = __shfl_sync(0xFFFFFFFFu, s, j);
                    int s1 = __shfl_sync(0xFFFFFFFFu, s, j + 1);
                    int s2 = __shfl_sync(0xFFFFFFFFu, s, j + 2);
                    int s3 = __shfl_sync(0xFFFFFFFFu, s, j + 3);
                    float w0 = __shfl_sync(0xFFFFFFFFu, w, j);
                    float w1 = __shfl_sync(0xFFFFFFFFu, w, j + 1);
                    float w2 = __shfl_sync(0xFFFFFFFFu, w, j + 2);
                    float w3 = __shfl_sync(0xFFFFFFFFu, w, j + 3);
                    float4 v0 = reinterpret_cast<const float4*>(H + (size_t)s0 * 128)[lane];
                    float4 v1 = reinterpret_cast<const float4*>(H + (size_t)s1 * 128)[lane];
                    float4 v2 = reinterpret_cast<const float4*>(H + (size_t)s2 * 128)[lane];
                    float4 v3 = reinterpret_cast<const float4*>(H + (size_t)s3 * 128)[lane];
                    acc.x += w0 * v0.x + w1 * v1.x + w2 * v2.x + w3 * v3.x;
                    acc.y += w0 * v0.y + w1 * v1.y + w2 * v2.y + w3 * v3.y;
                    acc.z += w0 * v0.z + w1 * v1.z + w2 * v2.z + w3 * v3.z;
                    acc.w += w0 * v0.w + w1 * v1.w + w2 * v2.w + w3 * v3.w;
                }
                for (; j < mm; j++) {
                    int sj = __shfl_sync(0xFFFFFFFFu, s, j);
                    float wj = __shfl_sync(0xFFFFFFFFu, w, j);
                    float4 v = reinterpret_cast<const float4*>(H + (size_t)sj * 128)[lane];
                    acc.x += wj * v.x; acc.y += wj * v.y;
                    acc.z += wj * v.z; acc.w += wj * v.w;
                }
            }
            float inv = 1.0f / fmaxf((float)d, 1.0f);
            uint32_t h0, l0, h1, l1;
            split_bf2(acc.x * inv, acc.y * inv, h0, l0);
            split_bf2(acc.z * inv, acc.w * inv, h1, l1);
            GfH[r * FW + 2 * lane]     = h0;
            GfH[r * FW + 2 * lane + 1] = h1;
            GfL[r * FW + 2 * lane]     = l0;
            GfL[r * FW + 2 * lane + 1] = l1;
        } else {
            float2 acc = make_float2(0.f, 0.f);
            for (int base = 0; base < d; base += 32) {
                int mm = min(32, d - base);
                int s = 0; float w = 0.f;
                if (lane < mm) {
                    int2 e = g_edge[start + base + lane];
                    s = e.x; w = __int_as_float(e.y);
                }
                int j = 0;
                for (; j + 4 <= mm; j += 4) {
                    int s0 = __shfl_sync(0xFFFFFFFFu, s, j);
                    int s1 = __shfl_sync(0xFFFFFFFFu, s, j + 1);
                    int s2 = __shfl_sync(0xFFFFFFFFu, s, j + 2);
                    int s3 = __shfl_sync(0xFFFFFFFFu, s, j + 3);
                    float w0 = __shfl_sync(0xFFFFFFFFu, w, j);
                    float w1 = __shfl_sync(0xFFFFFFFFu, w, j + 1);
                    float w2 = __shfl_sync(0xFFFFFFFFu, w, j + 2);
                    float w3 = __shfl_sync(0xFFFFFFFFu, w, j + 3);
                    float2 v0 = reinterpret_cast<const float2*>(H + (size_t)s0 * 64)[lane];
                    float2 v1 = reinterpret_cast<const float2*>(H + (size_t)s1 * 64)[lane];
                    float2 v2 = reinterpret_cast<const float2*>(H + (size_t)s2 * 64)[lane];
                    float2 v3 = reinterpret_cast<const float2*>(H + (size_t)s3 * 64)[lane];
                    acc.x += w0 * v0.x + w1 * v1.x + w2 * v2.x + w3 * v3.x;
                    acc.y += w0 * v0.y + w1 * v1.y + w2 * v2.y + w3 * v3.y;
                }
                for (; j < mm; j++) {
                    int sj = __shfl_sync(0xFFFFFFFFu, s, j);
                    float wj = __shfl_sync(0xFFFFFFFFu, w, j);
                    float2 v = reinterpret_cast<const float2*>(H + (size_t)sj * 64)[lane];
                    acc.x += wj * v.x; acc.y += wj * v.y;
                }
            }
            float inv = 1.0f / fmaxf((float)d, 1.0f);
            uint32_t h, l;
            split_bf2(acc.x * inv, acc.y * inv, h, l);
            GfH[r * FW + lane] = h;
            GfL[r * FW + lane] = l;
        }
    }
    __syncthreads();

    // ---------------- rel conv: A = Gf (FW), B = Wrel planes ----------------
    for (int ch = 0; ch < NCH; ch++) {
#pragma unroll
        for (int q = 0; q < 4; q++) {
            int id  = tid + NTHREADS * q;
            int row = id >> 3;
            int kw  = (id & 7) * 4;
            size_t bsrc = (size_t)woff_rel + (size_t)row * KTW + ch * 32 + kw;
            *reinterpret_cast<uint4*>(BsH + row * SW + kw) =
                *reinterpret_cast<const uint4*>(g_wh + bsrc);
            *reinterpret_cast<uint4*>(BsL + row * SW + kw) =
                *reinterpret_cast<const uint4*>(g_wl + bsrc);
        }
        __syncthreads();
#pragma unroll
        for (int kw0 = 0; kw0 < 32; kw0 += 8) {
            uint32_t ah[2][4], al[2][4];
#pragma unroll
            for (int mt = 0; mt < 2; mt++) {
                int ab = (wm + mt * 16 + gr) * FW + ch * 32 + kw0 + gc;
                ah[mt][0] = GfH[ab];
                ah[mt][1] = GfH[ab + 8 * FW];
                ah[mt][2] = GfH[ab + 4];
                ah[mt][3] = GfH[ab + 8 * FW + 4];
                al[mt][0] = GfL[ab];
                al[mt][1] = GfL[ab + 8 * FW];
                al[mt][2] = GfL[ab + 4];
                al[mt][3] = GfL[ab + 8 * FW + 4];
            }
#pragma unroll
            for (int nt = 0; nt < 8; nt++) {
                int col = wn + nt * 8 + gr;
                uint32_t bh[2], bl[2];
                bh[0] = BsH[col * SW + kw0 + gc];
                bh[1] = BsH[col * SW + kw0 + gc + 4];
                bl[0] = BsL[col * SW + kw0 + gc];
                bl[1] = BsL[col * SW + kw0 + gc + 4];
#pragma unroll
                for (int mt = 0; mt < 2; mt++) {
                    mma_bf16(c[mt][nt], ah[mt], bl);
                    mma_bf16(c[mt][nt], al[mt], bh);
                    mma_bf16(c[mt][nt], ah[mt], bh);
                }
            }
        }
        __syncthreads();
    }

    // ---------------- root conv: A loaded from H into Gf (SW stride) ----------------
    for (int ch = 0; ch < NCH; ch++) {
#pragma unroll
        for (int q = 0; q < 8; q++) {
            int id  = tid + NTHREADS * q;
            int row = id >> 4;
            int k   = (id & 15) * 4;
            int kw  = k >> 1;
            int grow = m0 + row;
            float4 va = make_float4(0.f, 0.f, 0.f, 0.f);
            if (grow < M)
                va = *reinterpret_cast<const float4*>(H + (size_t)grow * KTC + ch * 64 + k);
            uint32_t h0, l0, h1, l1;
            split_bf2(va.x, va.y, h0, l0);
            split_bf2(va.z, va.w, h1, l1);
            GfH[row * SW + kw]     = h0;
            GfH[row * SW + kw + 1] = h1;
            GfL[row * SW + kw]     = l0;
            GfL[row * SW + kw + 1] = l1;
        }
#pragma unroll
        for (int q = 0; q < 4; q++) {
            int id  = tid + NTHREADS * q;
            int row = id >> 3;
            int kw  = (id & 7) * 4;
            size_t bsrc = (size_t)woff_root + (size_t)row * KTW + ch * 32 + kw;
            *reinterpret_cast<uint4*>(BsH + row * SW + kw) =
                *reinterpret_cast<const uint4*>(g_wh + bsrc);
            *reinterpret_cast<uint4*>(BsL + row * SW + kw) =
                *reinterpret_cast<const uint4*>(g_wl + bsrc);
        }
        __syncthreads();
#pragma unroll
        for (int kw0 = 0; kw0 < 32; kw0 += 8) {
            uint32_t ah[2][4], al[2][4];
#pragma unroll
            for (int mt = 0; mt < 2; mt++) {
                int rlo = wm + mt * 16 + gr;
                ah[mt][0] = GfH[rlo * SW + kw0 + gc];
                ah[mt][1] = GfH[(rlo + 8) * SW + kw0 + gc];
                ah[mt][2] = GfH[rlo * SW + kw0 + gc + 4];
                ah[mt][3] = GfH[(rlo + 8) * SW + kw0 + gc + 4];
                al[mt][0] = GfL[rlo * SW + kw0 + gc];
                al[mt][1] = GfL[(rlo + 8) * SW + kw0 + gc];
                al[mt][2] = GfL[rlo * SW + kw0 + gc + 4];
                al[mt][3] = GfL[(rlo + 8) * SW + kw0 + gc + 4];
            }
#pragma unroll
            for (int nt = 0; nt < 8; nt++) {
                int col = wn + nt * 8 + gr;
                uint32_t bh[2], bl[2];
                bh[0] = BsH[col * SW + kw0 + gc];
                bh[1] = BsH[col * SW + kw0 + gc + 4];
                bl[0] = BsL[col * SW + kw0 + gc];
                bl[1] = BsL[col * SW + kw0 + gc + 4];
#pragma unroll
                for (int mt = 0; mt < 2; mt++) {
                    mma_bf16(c[mt][nt], ah[mt], bl);
                    mma_bf16(c[mt][nt], al[mt], bh);
                    mma_bf16(c[mt][nt], ah[mt], bh);
                }
            }
        }
        __syncthreads();
    }

    // ---------------- stash t = relu(c + bias1) into Gf (FW) ----------------
#pragma unroll
    for (int mt = 0; mt < 2; mt++) {
        int r0 = wm + mt * 16 + gr;
#pragma unroll
        for (int nt = 0; nt < 8; nt++) {
            int col  = wn + nt * 8 + 2 * gc;
            int colw = (wn >> 1) + nt * 4 + gc;
            float b0 = bias1[col], b1 = bias1[col + 1];
            uint32_t h, l;
            split_bf2(fmaxf(c[mt][nt][0] + b0, 0.f),
                      fmaxf(c[mt][nt][1] + b1, 0.f), h, l);
            GfH[r0 * FW + colw] = h;
            GfL[r0 * FW + colw] = l;
            split_bf2(fmaxf(c[mt][nt][2] + b0, 0.f),
                      fmaxf(c[mt][nt][3] + b1, 0.f), h, l);
            GfH[(r0 + 8) * FW + colw] = h;
            GfL[(r0 + 8) * FW + colw] = l;
            c[mt][nt][0] = c[mt][nt][1] = c[mt][nt][2] = c[mt][nt][3] = 0.f;
        }
    }

    // ---------------- readout (K=128, 2 chunks) ----------------
    for (int ch = 0; ch < 2; ch++) {
#pragma unroll
        for (int q = 0; q < 4; q++) {
            int id  = tid + NTHREADS * q;
            int row = id >> 3;
            int kw  = (id & 7) * 4;
            size_t bsrc = (size_t)woff3 + (size_t)row * 64 + ch * 32 + kw;
            *reinterpret_cast<uint4*>(BsH + row * SW + kw) =
                *reinterpret_cast<const uint4*>(g_wh + bsrc);
            *reinterpret_cast<uint4*>(BsL + row * SW + kw) =
                *reinterpret_cast<const uint4*>(g_wl + bsrc);
        }
        __syncthreads();
#pragma unroll
        for (int kw0 = 0; kw0 < 32; kw0 += 8) {
            uint32_t ah[2][4], al[2][4];
#pragma unroll
            for (int mt = 0; mt < 2; mt++) {
                int ab = (wm + mt * 16 + gr) * FW + ch * 32 + kw0 + gc;
                ah[mt][0] = GfH[ab];
                ah[mt][1] = GfH[ab + 8 * FW];
                ah[mt][2] = GfH[ab + 4];
                ah[mt][3] = GfH[ab + 8 * FW + 4];
                al[mt][0] = GfL[ab];
                al[mt][1] = GfL[ab + 8 * FW];
                al[mt][2] = GfL[ab + 4];
                al[mt][3] = GfL[ab + 8 * FW + 4];
            }
#pragma unroll
            for (int nt = 0; nt < 8; nt++) {
                int col = wn + nt * 8 + gr;
                uint32_t bh[2], bl[2];
                bh[0] = BsH[col * SW + kw0 + gc];
                bh[1] = BsH[col * SW + kw0 + gc + 4];
                bl[0] = BsL[col * SW + kw0 + gc];
                bl[1] = BsL[col * SW + kw0 + gc + 4];
#pragma unroll
                for (int mt = 0; mt < 2; mt++) {
                    mma_bf16(c[mt][nt], ah[mt], bl);
                    mma_bf16(c[mt][nt], al[mt], bh);
                    mma_bf16(c[mt][nt], ah[mt], bh);
                }
            }
        }
        __syncthreads();
    }

    // ---------------- epilogue ----------------
    if (!HEAD) {
#pragma unroll
        for (int mt = 0; mt < 2; mt++) {
            int rlo = m0 + wm + mt * 16 + gr;
            int rhi = rlo + 8;
#pragma unroll
            for (int nt = 0; nt < 8; nt++) {
                int col = wn + nt * 8 + 2 * gc;
                float b0 = bias2[col], b1 = bias2[col + 1];
                if (rlo < M) {
                    float2 o;
                    o.x = fmaxf(c[mt][nt][0] + b0, 0.f);
                    o.y = fmaxf(c[mt][nt][1] + b1, 0.f);
                    *reinterpret_cast<float2*>(Y + (size_t)rlo * HID + col) = o;
                }
                if (rhi < M) {
                    float2 o;
                    o.x = fmaxf(c[mt][nt][2] + b0, 0.f);
                    o.y = fmaxf(c[mt][nt][3] + b1, 0.f);
                    *reinterpret_cast<float2*>(Y + (size_t)rhi * HID + col) = o;
                }
            }
        }
    } else {
#pragma unroll
        for (int mt = 0; mt < 2; mt++) {
            float plo = 0.f, phi = 0.f;
#pragma unroll
            for (int nt = 0; nt < 8; nt++) {
                int col = wn + nt * 8 + 2 * gc;
                float b0 = bias2[col], b1 = bias2[col + 1];
                float w0 = Wprd[col], w1 = Wprd[col + 1];
                plo += fmaxf(c[mt][nt][0] + b0, 0.f) * w0 +
                       fmaxf(c[mt][nt][1] + b1, 0.f) * w1;
                phi += fmaxf(c[mt][nt][2] + b0, 0.f) * w0 +
                       fmaxf(c[mt][nt][3] + b1, 0.f) * w1;
            }
            plo += __shfl_xor_sync(0xFFFFFFFFu, plo, 1);
            plo += __shfl_xor_sync(0xFFFFFFFFu, plo, 2);
            phi += __shfl_xor_sync(0xFFFFFFFFu, phi, 1);
            phi += __shfl_xor_sync(0xFFFFFFFFu, phi, 2);
            if (gc == 0) {
                red[wm + mt * 16 + gr][warp & 1]     = plo;
                red[wm + mt * 16 + gr + 8][warp & 1] = phi;
            }
        }
        __syncthreads();
        if (tid < 128) {
            int row = m0 + tid;
            if (row < M) Y[row] = red[tid][0] + red[tid][1] + bprd[0];
        }
    }
}

// ---------------------------------------------------------------------------
#define GEMM_SMEM ((2 * 128 * SW + 2 * 128 * FW) * 4)

extern "C" void kernel_launch(void* const* d_in, const int* in_sizes, int n_in,
                              void* d_out, int out_size) {
    const float* x     = (const float*)d_in[0];   // (N,1,64)
    const int*   ei    = (const int*)d_in[1];     // (2,E) int32
    const float* ew    = (const float*)d_in[2];
    const float* Wrel0 = (const float*)d_in[3];
    const float* brel0 = (const float*)d_in[4];
    const float* Wroot0= (const float*)d_in[5];
    const float* Wro0  = (const float*)d_in[6];
    const float* bro0  = (const float*)d_in[7];
    const float* Wrel1 = (const float*)d_in[8];
    const float* brel1 = (const float*)d_in[9];
    const float* Wroot1= (const float*)d_in[10];
    const float* Wro1  = (const float*)d_in[11];
    const float* bro1  = (const float*)d_in[12];
    const float* Wprd  = (const float*)d_in[13];
    const float* bprd  = (const float*)d_in[14];
    float*       out   = (float*)d_out;

    int N = in_sizes[0] / IN_CH;  // 50000
    int E = in_sizes[2];          // 800000

    float* h2; cudaGetSymbolAddress((void**)&h2, g_h2);

    cudaFuncSetAttribute(fused_layer<IN_CH, false>, cudaFuncAttributeMaxDynamicSharedMemorySize, GEMM_SMEM);
    cudaFuncSetAttribute(fused_layer<HID,   true >, cudaFuncAttributeMaxDynamicSharedMemorySize, GEMM_SMEM);

    int gb = (N + 127) / 128;
    int nb_scan = (N + 1023) / 1024;   // 49

    // --- prep + CSR build ---
    prep<<<(N + 255) / 256, 256>>>(Wrel0, Wroot0, Wro0, Wrel1, Wroot1, Wro1, N);
    hist<<<(E + 255) / 256, 256>>>(ei, E);
    scan1<<<nb_scan, 1024>>>(N);
    scan3<<<(N + 255) / 256, 256>>>(N);
    fill<<<(E + 255) / 256, 256>>>(ei, ew, E);

    // --- layer 0 (gather + conv0 + ro0) -> h2 ---
    fused_layer<IN_CH, false><<<gb, NTHREADS, GEMM_SMEM>>>(
        x, WOFF_REL0, WOFF_ROOT0, brel0, WOFF_RO0, bro0, nullptr, nullptr, h2, N);

    // --- layer 1 (gather + conv1 + ro1 + head) -> out ---
    fused_layer<HID, true><<<gb, NTHREADS, GEMM_SMEM>>>(
        h2, WOFF_REL1, WOFF_ROOT1, brel1, WOFF_RO1, bro1, Wprd, bprd, out, N);
}

// round 13
// speedup vs baseline: 1.3315x; 1.3315x over previous
#include <cuda_runtime.h>
#include <cuda_bf16.h>
#include <cstdint>

#define N_NODES 50000
#define N_EDGES 800000
#define IN_CH 64
#define HID 128
#define NTHREADS 256

// Scratch (device globals -- no allocation allowed)
__device__ int   g_deg[N_NODES];
__device__ int   g_off[N_NODES];    // block-local exclusive offsets (add g_part)
__device__ int   g_cur[N_NODES];    // block-local fill cursors
__device__ int   g_part[64];
__device__ int   g_ctr;
__device__ int2  g_edge[N_EDGES];   // {src, bits(weight)}
__device__ float g_agg[N_NODES * HID];
__device__ float g_h2[N_NODES * HID];
__device__ uint32_t g_wh[40960], g_wl[40960];   // pre-split weight planes

// weight plane offsets (bf16x2 words)
#define WOFF_REL0  0
#define WOFF_ROOT0 4096
#define WOFF_RO0   8192
#define WOFF_REL1  16384
#define WOFF_ROOT1 24576
#define WOFF_RO1   32768

// ---------------------------------------------------------------------------
// bf16 helpers
// ---------------------------------------------------------------------------
__device__ __forceinline__ uint32_t pack_bf2(float a, float b) {
    __nv_bfloat162 t = __floats2bfloat162_rn(a, b);
    return *reinterpret_cast<uint32_t*>(&t);
}
__device__ __forceinline__ void split_bf2(float a, float b, uint32_t& hi, uint32_t& lo) {
    float ah = __bfloat162float(__float2bfloat16_rn(a));
    float bh = __bfloat162float(__float2bfloat16_rn(b));
    hi = pack_bf2(ah, bh);
    lo = pack_bf2(a - ah, b - bh);
}
__device__ __forceinline__ void mma_bf16(float c[4], const uint32_t a[4], const uint32_t b[2]) {
    asm volatile(
        "mma.sync.aligned.m16n8k16.row.col.f32.bf16.bf16.f32 "
        "{%0,%1,%2,%3}, {%4,%5,%6,%7}, {%8,%9}, {%0,%1,%2,%3};"
        : "+f"(c[0]), "+f"(c[1]), "+f"(c[2]), "+f"(c[3])
        : "r"(a[0]), "r"(a[1]), "r"(a[2]), "r"(a[3]), "r"(b[0]), "r"(b[1]));
}

// ---------------------------------------------------------------------------
// Prep: split weights into hi/lo planes; zero deg; zero ctr
// ---------------------------------------------------------------------------
__global__ void prep(const float* __restrict__ Wrel0, const float* __restrict__ Wroot0,
                     const float* __restrict__ Wro0,  const float* __restrict__ Wrel1,
                     const float* __restrict__ Wroot1,const float* __restrict__ Wro1, int n) {
    int i = blockIdx.x * blockDim.x + threadIdx.x;
    if (i < n) g_deg[i] = 0;
    if (i == 0) g_ctr = 0;
    if (i >= 40960) return;
    const float* src; int off;
    if      (i < 4096)  { src = Wrel0;  off = i; }
    else if (i < 8192)  { src = Wroot0; off = i - 4096; }
    else if (i < 16384) { src = Wro0;   off = i - 8192; }
    else if (i < 24576) { src = Wrel1;  off = i - 16384; }
    else if (i < 32768) { src = Wroot1; off = i - 24576; }
    else                { src = Wro1;   off = i - 32768; }
    float2 v = reinterpret_cast<const float2*>(src)[off];
    uint32_t h, l; split_bf2(v.x, v.y, h, l);
    g_wh[i] = h; g_wl[i] = l;
}

// ---------------------------------------------------------------------------
// CSR build: histogram -> shuffle scan (block-local + partials) -> fill
// Consumers add g_part[node >> 10] to block-local offsets.
// ---------------------------------------------------------------------------
__global__ void hist(const int* __restrict__ ei, int E) {
    int e = blockIdx.x * blockDim.x + threadIdx.x;
    if (e < E) atomicAdd(&g_deg[ei[E + e]], 1);
}
__global__ void scan1(int n) {
    __shared__ int wsum[32];
    __shared__ int s_total;
    __shared__ bool isLast;
    int tid  = threadIdx.x;
    int lane = tid & 31, wid = tid >> 5;
    int i = blockIdx.x * 1024 + tid;
    int v = (i < n) ? g_deg[i] : 0;
    int inc = v;
#pragma unroll
    for (int o = 1; o < 32; o <<= 1) {
        int t = __shfl_up_sync(0xFFFFFFFFu, inc, o);
        if (lane >= o) inc += t;
    }
    if (lane == 31) wsum[wid] = inc;
    __syncthreads();
    if (wid == 0) {
        int wv = wsum[lane];
        int winc = wv;
#pragma unroll
        for (int o = 1; o < 32; o <<= 1) {
            int t = __shfl_up_sync(0xFFFFFFFFu, winc, o);
            if (lane >= o) winc += t;
        }
        wsum[lane] = winc - wv;          // exclusive warp offset
        if (lane == 31) s_total = winc;  // block total
    }
    __syncthreads();
    if (i < n) {
        int loc = inc - v + wsum[wid];   // block-local exclusive
        g_off[i] = loc;
        g_cur[i] = loc;
    }
    if (tid == 0) g_part[blockIdx.x] = s_total;
    __threadfence();
    if (tid == 0) isLast = (atomicAdd(&g_ctr, 1) == (int)gridDim.x - 1);
    __syncthreads();
    if (isLast) {
        __shared__ int p[64];
        int nb = gridDim.x;
        if (tid < 64) p[tid] = (tid < nb) ? g_part[tid] : 0;
        __syncthreads();
        if (tid == 0) {
            int run = 0;
            for (int b = 0; b < nb; b++) { int t = p[b]; p[b] = run; run += t; }
        }
        __syncthreads();
        if (tid < nb) g_part[tid] = p[tid];
    }
}
__global__ void fill(const int* __restrict__ ei, const float* __restrict__ ew, int E) {
    int e = blockIdx.x * blockDim.x + threadIdx.x;
    if (e >= E) return;
    int dst = ei[E + e];
    int p = atomicAdd(&g_cur[dst], 1) + g_part[dst >> 10];
    g_edge[p] = make_int2(ei[e], __float_as_int(ew[e]));
}

// ---------------------------------------------------------------------------
// Gather: one warp per dst node; agg[n] = (sum_e w_e * h[src_e]) / max(deg,1)
// ---------------------------------------------------------------------------
__global__ void gather64(const float* __restrict__ h, int N) {
    int warp = (blockIdx.x * blockDim.x + threadIdx.x) >> 5;
    int lane = threadIdx.x & 31;
    if (warp >= N) return;
    int start = g_off[warp] + g_part[warp >> 10];
    int d = g_deg[warp];
    float2 acc = make_float2(0.f, 0.f);
    for (int base = 0; base < d; base += 32) {
        int m = min(32, d - base);
        int s = 0; float w = 0.f;
        if (lane < m) {
            int2 e = g_edge[start + base + lane];
            s = e.x; w = __int_as_float(e.y);
        }
        for (int j = 0; j < m; j++) {
            int sj = __shfl_sync(0xFFFFFFFFu, s, j);
            float wj = __shfl_sync(0xFFFFFFFFu, w, j);
            float2 v = reinterpret_cast<const float2*>(h + (size_t)sj * IN_CH)[lane];
            acc.x += wj * v.x;
            acc.y += wj * v.y;
        }
    }
    float inv = 1.0f / fmaxf((float)d, 1.0f);
    reinterpret_cast<float2*>(g_agg + (size_t)warp * IN_CH)[lane] =
        make_float2(acc.x * inv, acc.y * inv);
}

__global__ void gather128(const float* __restrict__ h, int N) {
    int warp = (blockIdx.x * blockDim.x + threadIdx.x) >> 5;
    int lane = threadIdx.x & 31;
    if (warp >= N) return;
    int start = g_off[warp] + g_part[warp >> 10];
    int d = g_deg[warp];
    float4 acc = make_float4(0.f, 0.f, 0.f, 0.f);
    for (int base = 0; base < d; base += 32) {
        int m = min(32, d - base);
        int s = 0; float w = 0.f;
        if (lane < m) {
            int2 e = g_edge[start + base + lane];
            s = e.x; w = __int_as_float(e.y);
        }
        for (int j = 0; j < m; j++) {
            int sj = __shfl_sync(0xFFFFFFFFu, s, j);
            float wj = __shfl_sync(0xFFFFFFFFu, w, j);
            float4 v = reinterpret_cast<const float4*>(h + (size_t)sj * HID)[lane];
            acc.x += wj * v.x; acc.y += wj * v.y;
            acc.z += wj * v.z; acc.w += wj * v.w;
        }
    }
    float inv = 1.0f / fmaxf((float)d, 1.0f);
    reinterpret_cast<float4*>(g_agg + (size_t)warp * HID)[lane] =
        make_float4(acc.x * inv, acc.y * inv, acc.z * inv, acc.w * inv);
}

// ---------------------------------------------------------------------------
// Fused dual-GEMM (3xBF16 mma), weights pre-split in global planes:
//   t  = relu( A1@W1^T + A2@W2^T + bias1 )   (conv; KTC = 64 or 128)
//   y  = relu( t@W3^T + bias2 )              (readout; K = 128)
//   HEAD: out[m] = sum_n y[m,n] * Wprd[n] + bprd
// CTA 128x128, 8 warps (4x2), warp tile 32x64 (2x8 m16n8k16).
// ---------------------------------------------------------------------------
#define SW 36    // conv tile stride (words)
#define FW 68    // full-width ro A tile stride (words)

template <int KTC, bool HEAD>
__global__ void __launch_bounds__(NTHREADS, 2)
fused_gemm(const float* __restrict__ A1, int woff1,
           const float* __restrict__ A2, int woff2,
           const float* __restrict__ bias1,
           int woff3, const float* __restrict__ bias2,
           const float* __restrict__ Wprd, const float* __restrict__ bprd,
           float* __restrict__ Y, int M)
{
    extern __shared__ uint32_t sm[];
    uint32_t* BsH = sm;                    // [128][SW]
    uint32_t* BsL = sm + 128 * SW;
    uint32_t* AfH = sm + 2 * 128 * SW;     // [128][FW]; conv phase uses stride SW
    uint32_t* AfL = sm + 2 * 128 * SW + 128 * FW;
    __shared__ float red[128][2];

    int tid  = threadIdx.x;
    int lane = tid & 31;
    int warp = tid >> 5;
    int wm   = (warp >> 1) * 32;
    int wn   = (warp & 1) * 64;
    int gr   = lane >> 2;
    int gc   = lane & 3;
    int m0   = blockIdx.x * 128;

    constexpr int KTW = KTC / 2;           // weight plane words per row (conv mats)

    float c[2][8][4];
#pragma unroll
    for (int mt = 0; mt < 2; mt++)
#pragma unroll
        for (int nt = 0; nt < 8; nt++)
#pragma unroll
            for (int j = 0; j < 4; j++) c[mt][nt][j] = 0.0f;

    // ---------------- conv phase ----------------
    constexpr int NCH = KTC / 64;
    const int NPH = 2 * NCH;
    for (int ph = 0; ph < NPH; ph++) {
        int srcidx = ph / NCH;
        int ch     = ph % NCH;
        const float* A = srcidx ? A2 : A1;
        int woff = srcidx ? woff2 : woff1;
        if (ph) __syncthreads();

        // A: fp32 -> hi/lo split (8 float4 / thread)
#pragma unroll
        for (int q = 0; q < 8; q++) {
            int id  = tid + NTHREADS * q;
            int row = id >> 4;            // 16 float4 per row
            int k   = (id & 15) * 4;
            int kw  = k >> 1;
            int grow = m0 + row;
            float4 va = make_float4(0.f, 0.f, 0.f, 0.f);
            if (grow < M)
                va = *reinterpret_cast<const float4*>(A + (size_t)grow * KTC + ch * 64 + k);
            uint32_t h0, l0, h1, l1;
            split_bf2(va.x, va.y, h0, l0);
            split_bf2(va.z, va.w, h1, l1);
            AfH[row * SW + kw]     = h0;
            AfH[row * SW + kw + 1] = h1;
            AfL[row * SW + kw]     = l0;
            AfL[row * SW + kw + 1] = l1;
        }
        // B: pure copy from pre-split planes
#pragma unroll
        for (int q = 0; q < 4; q++) {
            int id  = tid + NTHREADS * q;     // 0..1023
            int row = id >> 3;                // 8 uint4 per row
            int kw  = (id & 7) * 4;
            size_t bsrc = (size_t)woff + (size_t)row * KTW + ch * 32 + kw;
            *reinterpret_cast<uint4*>(BsH + row * SW + kw) =
                *reinterpret_cast<const uint4*>(g_wh + bsrc);
            *reinterpret_cast<uint4*>(BsL + row * SW + kw) =
                *reinterpret_cast<const uint4*>(g_wl + bsrc);
        }
        __syncthreads();

#pragma unroll
        for (int kw0 = 0; kw0 < 32; kw0 += 8) {
            uint32_t ah[2][4], al[2][4];
#pragma unroll
            for (int mt = 0; mt < 2; mt++) {
                int rlo = wm + mt * 16 + gr;
                ah[mt][0] = AfH[rlo * SW + kw0 + gc];
                ah[mt][1] = AfH[(rlo + 8) * SW + kw0 + gc];
                ah[mt][2] = AfH[rlo * SW + kw0 + gc + 4];
                ah[mt][3] = AfH[(rlo + 8) * SW + kw0 + gc + 4];
                al[mt][0] = AfL[rlo * SW + kw0 + gc];
                al[mt][1] = AfL[(rlo + 8) * SW + kw0 + gc];
                al[mt][2] = AfL[rlo * SW + kw0 + gc + 4];
                al[mt][3] = AfL[(rlo + 8) * SW + kw0 + gc + 4];
            }
#pragma unroll
            for (int nt = 0; nt < 8; nt++) {
                int col = wn + nt * 8 + gr;
                uint32_t bh[2], bl[2];
                bh[0] = BsH[col * SW + kw0 + gc];
                bh[1] = BsH[col * SW + kw0 + gc + 4];
                bl[0] = BsL[col * SW + kw0 + gc];
                bl[1] = BsL[col * SW + kw0 + gc + 4];
#pragma unroll
                for (int mt = 0; mt < 2; mt++) {
                    mma_bf16(c[mt][nt], ah[mt], bl);
                    mma_bf16(c[mt][nt], al[mt], bh);
                    mma_bf16(c[mt][nt], ah[mt], bh);
                }
            }
        }
    }

    // ---------------- stash t = relu(c + bias1) into full-width tile ----------------
    __syncthreads();
#pragma unroll
    for (int mt = 0; mt < 2; mt++) {
        int r0 = wm + mt * 16 + gr;
#pragma unroll
        for (int nt = 0; nt < 8; nt++) {
            int col  = wn + nt * 8 + 2 * gc;
            int colw = (wn >> 1) + nt * 4 + gc;
            float b0 = bias1[col], b1 = bias1[col + 1];
            uint32_t h, l;
            split_bf2(fmaxf(c[mt][nt][0] + b0, 0.f),
                      fmaxf(c[mt][nt][1] + b1, 0.f), h, l);
            AfH[r0 * FW + colw] = h;
            AfL[r0 * FW + colw] = l;
            split_bf2(fmaxf(c[mt][nt][2] + b0, 0.f),
                      fmaxf(c[mt][nt][3] + b1, 0.f), h, l);
            AfH[(r0 + 8) * FW + colw] = h;
            AfL[(r0 + 8) * FW + colw] = l;
            c[mt][nt][0] = c[mt][nt][1] = c[mt][nt][2] = c[mt][nt][3] = 0.f;
        }
    }

    // ---------------- readout phase (K=128, 2 chunks) ----------------
    for (int ch = 0; ch < 2; ch++) {
#pragma unroll
        for (int q = 0; q < 4; q++) {
            int id  = tid + NTHREADS * q;
            int row = id >> 3;
            int kw  = (id & 7) * 4;
            size_t bsrc = (size_t)woff3 + (size_t)row * 64 + ch * 32 + kw;
            *reinterpret_cast<uint4*>(BsH + row * SW + kw) =
                *reinterpret_cast<const uint4*>(g_wh + bsrc);
            *reinterpret_cast<uint4*>(BsL + row * SW + kw) =
                *reinterpret_cast<const uint4*>(g_wl + bsrc);
        }
        __syncthreads();

#pragma unroll
        for (int kw0 = 0; kw0 < 32; kw0 += 8) {
            uint32_t ah[2][4], al[2][4];
#pragma unroll
            for (int mt = 0; mt < 2; mt++) {
                int rlo = wm + mt * 16 + gr;
                int ab  = rlo * FW + ch * 32 + kw0 + gc;
                ah[mt][0] = AfH[ab];
                ah[mt][1] = AfH[ab + 8 * FW];
                ah[mt][2] = AfH[ab + 4];
                ah[mt][3] = AfH[ab + 8 * FW + 4];
                al[mt][0] = AfL[ab];
                al[mt][1] = AfL[ab + 8 * FW];
                al[mt][2] = AfL[ab + 4];
                al[mt][3] = AfL[ab + 8 * FW + 4];
            }
#pragma unroll
            for (int nt = 0; nt < 8; nt++) {
                int col = wn + nt * 8 + gr;
                uint32_t bh[2], bl[2];
                bh[0] = BsH[col * SW + kw0 + gc];
                bh[1] = BsH[col * SW + kw0 + gc + 4];
                bl[0] = BsL[col * SW + kw0 + gc];
                bl[1] = BsL[col * SW + kw0 + gc + 4];
#pragma unroll
                for (int mt = 0; mt < 2; mt++) {
                    mma_bf16(c[mt][nt], ah[mt], bl);
                    mma_bf16(c[mt][nt], al[mt], bh);
                    mma_bf16(c[mt][nt], ah[mt], bh);
                }
            }
        }
        __syncthreads();
    }

    // ---------------- epilogue ----------------
    if (!HEAD) {
#pragma unroll
        for (int mt = 0; mt < 2; mt++) {
            int rlo = m0 + wm + mt * 16 + gr;
            int rhi = rlo + 8;
#pragma unroll
            for (int nt = 0; nt < 8; nt++) {
                int col = wn + nt * 8 + 2 * gc;
                float b0 = bias2[col], b1 = bias2[col + 1];
                if (rlo < M) {
                    float2 o;
                    o.x = fmaxf(c[mt][nt][0] + b0, 0.f);
                    o.y = fmaxf(c[mt][nt][1] + b1, 0.f);
                    *reinterpret_cast<float2*>(Y + (size_t)rlo * HID + col) = o;
                }
                if (rhi < M) {
                    float2 o;
                    o.x = fmaxf(c[mt][nt][2] + b0, 0.f);
                    o.y = fmaxf(c[mt][nt][3] + b1, 0.f);
                    *reinterpret_cast<float2*>(Y + (size_t)rhi * HID + col) = o;
                }
            }
        }
    } else {
#pragma unroll
        for (int mt = 0; mt < 2; mt++) {
            float plo = 0.f, phi = 0.f;
#pragma unroll
            for (int nt = 0; nt < 8; nt++) {
                int col = wn + nt * 8 + 2 * gc;
                float b0 = bias2[col], b1 = bias2[col + 1];
                float w0 = Wprd[col], w1 = Wprd[col + 1];
                plo += fmaxf(c[mt][nt][0] + b0, 0.f) * w0 +
                       fmaxf(c[mt][nt][1] + b1, 0.f) * w1;
                phi += fmaxf(c[mt][nt][2] + b0, 0.f) * w0 +
                       fmaxf(c[mt][nt][3] + b1, 0.f) * w1;
            }
            plo += __shfl_xor_sync(0xFFFFFFFFu, plo, 1);
            plo += __shfl_xor_sync(0xFFFFFFFFu, plo, 2);
            phi += __shfl_xor_sync(0xFFFFFFFFu, phi, 1);
            phi += __shfl_xor_sync(0xFFFFFFFFu, phi, 2);
            if (gc == 0) {
                red[wm + mt * 16 + gr][warp & 1]     = plo;
                red[wm + mt * 16 + gr + 8][warp & 1] = phi;
            }
        }
        __syncthreads();
        if (tid < 128) {
            int row = m0 + tid;
            if (row < M) Y[row] = red[tid][0] + red[tid][1] + bprd[0];
        }
    }
}

// ---------------------------------------------------------------------------
#define GEMM_SMEM ((2 * 128 * SW + 2 * 128 * FW) * 4)

extern "C" void kernel_launch(void* const* d_in, const int* in_sizes, int n_in,
                              void* d_out, int out_size) {
    const float* x     = (const float*)d_in[0];   // (N,1,64)
    const int*   ei    = (const int*)d_in[1];     // (2,E) int32
    const float* ew    = (const float*)d_in[2];
    const float* Wrel0 = (const float*)d_in[3];
    const float* brel0 = (const float*)d_in[4];
    const float* Wroot0= (const float*)d_in[5];
    const float* Wro0  = (const float*)d_in[6];
    const float* bro0  = (const float*)d_in[7];
    const float* Wrel1 = (const float*)d_in[8];
    const float* brel1 = (const float*)d_in[9];
    const float* Wroot1= (const float*)d_in[10];
    const float* Wro1  = (const float*)d_in[11];
    const float* bro1  = (const float*)d_in[12];
    const float* Wprd  = (const float*)d_in[13];
    const float* bprd  = (const float*)d_in[14];
    float*       out   = (float*)d_out;

    int N = in_sizes[0] / IN_CH;  // 50000
    int E = in_sizes[2];          // 800000

    float* agg; cudaGetSymbolAddress((void**)&agg, g_agg);
    float* h2;  cudaGetSymbolAddress((void**)&h2,  g_h2);

    cudaFuncSetAttribute(fused_gemm<IN_CH, false>, cudaFuncAttributeMaxDynamicSharedMemorySize, GEMM_SMEM);
    cudaFuncSetAttribute(fused_gemm<HID,   true >, cudaFuncAttributeMaxDynamicSharedMemorySize, GEMM_SMEM);

    int gb = (N + 127) / 128;
    int nb_scan = (N + 1023) / 1024;   // 49

    // --- prep + CSR build ---
    prep<<<(N + 255) / 256, 256>>>(Wrel0, Wroot0, Wro0, Wrel1, Wroot1, Wro1, N);
    hist<<<(E + 255) / 256, 256>>>(ei, E);
    scan1<<<nb_scan, 1024>>>(N);
    fill<<<(E + 255) / 256, 256>>>(ei, ew, E);

    // --- layer 0 (conv0 + ro0 fused) -> h2 ---
    gather64<<<(N * 32 + 255) / 256, 256>>>(x, N);
    fused_gemm<IN_CH, false><<<gb, NTHREADS, GEMM_SMEM>>>(
        agg, WOFF_REL0, x, WOFF_ROOT0, brel0, WOFF_RO0, bro0, nullptr, nullptr, h2, N);

    // --- layer 1 (conv1 + ro1 + head fused) -> out ---
    gather128<<<(N * 32 + 255) / 256, 256>>>(h2, N);
    fused_gemm<HID, true><<<gb, NTHREADS, GEMM_SMEM>>>(
        agg, WOFF_REL1, h2, WOFF_ROOT1, brel1, WOFF_RO1, bro1, Wprd, bprd, out, N);
}